// round 2
// baseline (speedup 1.0000x reference)
#include <cuda_runtime.h>
#include <cuda_bf16.h>
#include <math.h>

// Problem constants
#define B_  2
#define N_  2048
#define DIM_ 1024
#define H_  16
#define DH_ 64
#define BH_ (B_*H_)            // 32
#define ROWS_ (B_*N_)          // 4096
#define MAT_ELEMS ((size_t)N_*DH_)   // 131072 = 1<<17
#define EPS_ 1.1920929e-07f

// ---------------------------------------------------------------------------
// Scratch (allocation-free: __device__ globals)
// ---------------------------------------------------------------------------
__device__ float g_x[(size_t)ROWS_*DIM_];          // rmsnorm'd tokens
__device__ float g_q[(size_t)BH_*N_*DH_];          // (b,h,n,d)
__device__ float g_k[(size_t)3*BH_*N_*DH_];        // (e,b,h,n,d)
__device__ float g_v[(size_t)3*BH_*N_*DH_];
__device__ float g_n[(size_t)3*BH_*N_*DH_];        // nq|nk|nv slabs
__device__ float g_o[(size_t)BH_*N_*DH_];          // outer attend output
__device__ float g_cos[N_*32];
__device__ float g_sin[N_*32];

// ---------------------------------------------------------------------------
// RMSNorm over DIM=1024 (one block per row)
// ---------------------------------------------------------------------------
__global__ void rmsnorm_dim_kernel(const float* __restrict__ in,
                                   const float* __restrict__ w,
                                   float* __restrict__ out) {
    int row = blockIdx.x;
    const float* p = in + (size_t)row * DIM_;
    float s = 0.f;
    for (int i = threadIdx.x; i < DIM_; i += 256) { float v = p[i]; s += v*v; }
    __shared__ float sm[8];
    for (int o = 16; o > 0; o >>= 1) s += __shfl_xor_sync(~0u, s, o);
    if ((threadIdx.x & 31) == 0) sm[threadIdx.x >> 5] = s;
    __syncthreads();
    if (threadIdx.x < 8) {
        s = sm[threadIdx.x];
        for (int o = 4; o > 0; o >>= 1) s += __shfl_xor_sync(0xffu, s, o);
        if (threadIdx.x == 0) sm[0] = s;
    }
    __syncthreads();
    float inv = rsqrtf(sm[0] * (1.f/DIM_) + EPS_);
    for (int i = threadIdx.x; i < DIM_; i += 256)
        out[(size_t)row*DIM_ + i] = p[i] * inv * w[i];
}

// ---------------------------------------------------------------------------
// RMSNorm over DH=64 (one warp per row), optional per-slab weight (e = row/65536)
// ---------------------------------------------------------------------------
__global__ void rmsnorm_dh_kernel(float* __restrict__ x, const float* __restrict__ w,
                                  int use_e, int total_rows) {
    int warp = (blockIdx.x * blockDim.x + threadIdx.x) >> 5;
    if (warp >= total_rows) return;
    int lane = threadIdx.x & 31;
    float* p = x + (size_t)warp * DH_;
    float a = p[lane], b = p[lane + 32];
    float s = a*a + b*b;
    for (int o = 16; o > 0; o >>= 1) s += __shfl_xor_sync(~0u, s, o);
    float inv = rsqrtf(s * (1.f/DH_) + EPS_);
    const float* ww = w + (use_e ? (warp / (BH_*N_)) * DH_ : 0);
    p[lane]      = a * inv * ww[lane];
    p[lane + 32] = b * inv * ww[lane + 32];
}

// ---------------------------------------------------------------------------
// RoPE table + in-place RoPE apply (layout ...,N,DH so n = row % N)
// ---------------------------------------------------------------------------
__global__ void rope_table_kernel() {
    int idx = blockIdx.x * blockDim.x + threadIdx.x;
    if (idx >= N_*32) return;
    int n = idx >> 5, t = idx & 31;
    float inv_freq = powf(10000.f, -(2.f * (float)t) / 64.f);
    float ang = (float)n * inv_freq;
    g_cos[idx] = cosf(ang);
    g_sin[idx] = sinf(ang);
}

__global__ void rope_kernel(float* __restrict__ x, int total_rows) {
    int idx = blockIdx.x * blockDim.x + threadIdx.x;
    if (idx >= total_rows * 32) return;
    int row = idx >> 5, t = idx & 31;
    int n = row & (N_-1);
    float c = g_cos[(n<<5) + t], s = g_sin[(n<<5) + t];
    float* p = x + ((size_t)row << 6) + (t << 1);
    float2 v = *(float2*)p;
    float2 r; r.x = v.x*c - v.y*s; r.y = v.y*c + v.x*s;
    *(float2*)p = r;
}

// ---------------------------------------------------------------------------
// SGEMM 64x64x16 tiles, 256 threads, 4x4 micro-tile
// AMODE: 0 = A row-major (M x K), 1 = gather from g_o layout (b,h,n,d)->(bn, hd)
// CMODE: 0 = plain row-major, 1 = q layout (b,h,n,d), 2 = kv layout (e,b,h,n,d)
// ---------------------------------------------------------------------------
template<int AMODE, int CMODE>
__global__ void sgemm_kernel(const float* __restrict__ A, const float* __restrict__ Bm,
                             float* __restrict__ C, int M, int K, int Nc) {
    __shared__ float As[16][64];
    __shared__ float Bs[16][68];
    int tx = threadIdx.x;
    int brow = blockIdx.y * 64, bcol = blockIdx.x * 64;
    int lr = tx >> 2, lc4 = (tx & 3) << 2;   // A tile load coords
    int br = tx >> 4, bc4 = (tx & 15) << 2;  // B tile load coords
    int trow = (tx >> 4) << 2, tcol = (tx & 15) << 2;
    float acc[4][4];
    #pragma unroll
    for (int i = 0; i < 4; i++)
        #pragma unroll
        for (int j = 0; j < 4; j++) acc[i][j] = 0.f;

    for (int k0 = 0; k0 < K; k0 += 16) {
        float4 av;
        if (AMODE == 0) {
            av = *(const float4*)&A[(size_t)(brow + lr) * K + k0 + lc4];
        } else {
            int row = brow + lr;
            int b = row >> 11, n = row & (N_-1);
            int kk = k0 + lc4;
            int h = kk >> 6, d = kk & 63;
            av = *(const float4*)&A[((((size_t)b*H_ + h)*N_ + n) << 6) + d];
        }
        As[lc4+0][lr] = av.x; As[lc4+1][lr] = av.y;
        As[lc4+2][lr] = av.z; As[lc4+3][lr] = av.w;
        *(float4*)&Bs[br][bc4] = *(const float4*)&Bm[(size_t)(k0 + br) * Nc + bcol + bc4];
        __syncthreads();
        #pragma unroll
        for (int k = 0; k < 16; k++) {
            float4 a = *(float4*)&As[k][trow];
            float4 b4 = *(float4*)&Bs[k][tcol];
            acc[0][0] += a.x*b4.x; acc[0][1] += a.x*b4.y; acc[0][2] += a.x*b4.z; acc[0][3] += a.x*b4.w;
            acc[1][0] += a.y*b4.x; acc[1][1] += a.y*b4.y; acc[1][2] += a.y*b4.z; acc[1][3] += a.y*b4.w;
            acc[2][0] += a.z*b4.x; acc[2][1] += a.z*b4.y; acc[2][2] += a.z*b4.z; acc[2][3] += a.z*b4.w;
            acc[3][0] += a.w*b4.x; acc[3][1] += a.w*b4.y; acc[3][2] += a.w*b4.z; acc[3][3] += a.w*b4.w;
        }
        __syncthreads();
    }
    #pragma unroll
    for (int i = 0; i < 4; i++) {
        int row = brow + trow + i;
        int b = row >> 11, n = row & (N_-1);
        #pragma unroll
        for (int j = 0; j < 4; j++) {
            int col = bcol + tcol + j;
            if (CMODE == 0) {
                C[(size_t)row * Nc + col] = acc[i][j];
            } else if (CMODE == 1) {
                int h = col >> 6, d = col & 63;
                C[((((size_t)b*H_ + h)*N_ + n) << 6) + d] = acc[i][j];
            } else {
                int e = col >> 10, h = (col >> 6) & 15, d = col & 63;
                C[(((((size_t)e*B_ + b)*H_ + h)*N_ + n) << 6) + d] = acc[i][j];
            }
        }
    }
}

// ---------------------------------------------------------------------------
// Causal flash attention: 1 query row per thread, 128 q-rows/block,
// K/V tiles 32x64 in smem, online softmax per 16-key subtile.
// grid = (N/128, BH, n_e). Q indexed by blockIdx.y only (shared across e).
// ---------------------------------------------------------------------------
__global__ __launch_bounds__(128) void attn_kernel(const float* __restrict__ Q,
                                                   const float* __restrict__ K,
                                                   const float* __restrict__ V,
                                                   float* __restrict__ O) {
    __shared__ float ks[32*64];
    __shared__ float vs[32*64];
    size_t mat = blockIdx.y + (size_t)blockIdx.z * BH_;
    const float* q = Q + ((size_t)blockIdx.y << 17);
    const float* k = K + (mat << 17);
    const float* v = V + (mat << 17);
    float*       o = O + (mat << 17);
    int qi = blockIdx.x * 128 + threadIdx.x;

    float qr[64];
    #pragma unroll
    for (int d = 0; d < 64; d += 4) {
        float4 t = *(const float4*)&q[((size_t)qi << 6) + d];
        qr[d] = t.x; qr[d+1] = t.y; qr[d+2] = t.z; qr[d+3] = t.w;
    }
    float m = -INFINITY, l = 0.f;
    float acc[64];
    #pragma unroll
    for (int d = 0; d < 64; d++) acc[d] = 0.f;

    int kend = blockIdx.x * 128 + 128;
    for (int k0 = 0; k0 < kend; k0 += 32) {
        __syncthreads();
        #pragma unroll
        for (int i = threadIdx.x * 4; i < 32*64; i += 128*4) {
            *(float4*)&ks[i] = *(const float4*)&k[((size_t)k0 << 6) + i];
            *(float4*)&vs[i] = *(const float4*)&v[((size_t)k0 << 6) + i];
        }
        __syncthreads();
        #pragma unroll
        for (int sub = 0; sub < 32; sub += 16) {
            float s[16];
            float mt = m;
            #pragma unroll
            for (int j = 0; j < 16; j++) {
                float dot = 0.f;
                const float* kr = &ks[(sub + j) << 6];
                #pragma unroll
                for (int d = 0; d < 64; d += 4) {
                    float4 kk = *(const float4*)&kr[d];
                    dot += qr[d]*kk.x + qr[d+1]*kk.y + qr[d+2]*kk.z + qr[d+3]*kk.w;
                }
                s[j] = (k0 + sub + j <= qi) ? dot * 0.125f : -INFINITY;
                mt = fmaxf(mt, s[j]);
            }
            float corr = __expf(m - mt);
            m = mt;
            l *= corr;
            #pragma unroll
            for (int d = 0; d < 64; d++) acc[d] *= corr;
            #pragma unroll
            for (int j = 0; j < 16; j++) {
                float p = __expf(s[j] - m);
                l += p;
                const float* vr = &vs[(sub + j) << 6];
                #pragma unroll
                for (int d = 0; d < 64; d += 4) {
                    float4 vv = *(const float4*)&vr[d];
                    acc[d]   += p*vv.x; acc[d+1] += p*vv.y;
                    acc[d+2] += p*vv.z; acc[d+3] += p*vv.w;
                }
            }
        }
    }
    float inv = 1.f / l;
    #pragma unroll
    for (int d = 0; d < 64; d += 4) {
        float4 t;
        t.x = acc[d]*inv; t.y = acc[d+1]*inv; t.z = acc[d+2]*inv; t.w = acc[d+3]*inv;
        *(float4*)&o[((size_t)qi << 6) + d] = t;
    }
}

// ---------------------------------------------------------------------------
// Launch
// ---------------------------------------------------------------------------
extern "C" void kernel_launch(void* const* d_in, const int* in_sizes, int n_in,
                              void* d_out, int out_size) {
    const float* tokens        = (const float*)d_in[0];
    const float* w_norm        = (const float*)d_in[1];
    const float* w_q           = (const float*)d_in[2];
    const float* w_k           = (const float*)d_in[3];
    const float* w_v           = (const float*)d_in[4];
    const float* w_key_norms   = (const float*)d_in[5];
    const float* w_nested_knorm= (const float*)d_in[6];
    const float* w_out         = (const float*)d_in[7];
    float* out = (float*)d_out;

    float *px, *pq, *pk, *pv, *pn, *po;
    cudaGetSymbolAddress((void**)&px, g_x);
    cudaGetSymbolAddress((void**)&pq, g_q);
    cudaGetSymbolAddress((void**)&pk, g_k);
    cudaGetSymbolAddress((void**)&pv, g_v);
    cudaGetSymbolAddress((void**)&pn, g_n);
    cudaGetSymbolAddress((void**)&po, g_o);

    // 1) x = rmsnorm(tokens)
    rmsnorm_dim_kernel<<<ROWS_, 256>>>(tokens, w_norm, px);
    // 2) rope tables
    rope_table_kernel<<<(N_*32 + 255)/256, 256>>>();
    // 3) q/k/v projections with layout-transposing epilogues
    sgemm_kernel<0,1><<<dim3(DIM_/64, ROWS_/64), 256>>>(px, w_q, pq, ROWS_, DIM_, DIM_);
    sgemm_kernel<0,2><<<dim3(3*DIM_/64, ROWS_/64), 256>>>(px, w_k, pk, ROWS_, DIM_, 3*DIM_);
    sgemm_kernel<0,2><<<dim3(3*DIM_/64, ROWS_/64), 256>>>(px, w_v, pv, ROWS_, DIM_, 3*DIM_);
    // 4) key rmsnorm (per-slab weight), then rope q and all k slabs
    {
        int rows = 3*BH_*N_;
        rmsnorm_dh_kernel<<<(rows*32 + 255)/256, 256>>>(pk, w_key_norms, 1, rows);
        rope_kernel<<<(BH_*N_*32 + 255)/256, 256>>>(pq, BH_*N_);
        rope_kernel<<<(rows*32 + 255)/256, 256>>>(pk, rows);
    }
    // 5) three inner causal attentions -> nq|nk|nv
    attn_kernel<<<dim3(N_/128, BH_, 3), 128>>>(pq, pk, pv, pn);
    // 6) nk rmsnorm, rope nq & nk
    {
        float* pnq = pn;
        float* pnk = pn + (size_t)BH_*N_*DH_;
        int rows = BH_*N_;
        rmsnorm_dh_kernel<<<(rows*32 + 255)/256, 256>>>(pnk, w_nested_knorm, 0, rows);
        rope_kernel<<<(rows*32 + 255)/256, 256>>>(pnq, rows);
        rope_kernel<<<(rows*32 + 255)/256, 256>>>(pnk, rows);
    }
    // 7) outer causal attention: attend(nq, nk, nv) -> g_o
    {
        float* pnq = pn;
        float* pnk = pn + (size_t)BH_*N_*DH_;
        float* pnv = pn + (size_t)2*BH_*N_*DH_;
        attn_kernel<<<dim3(N_/128, BH_, 1), 128>>>(pnq, pnk, pnv, po);
    }
    // 8) output projection with gathered A (transpose fold)
    sgemm_kernel<1,0><<<dim3(DIM_/64, ROWS_/64), 256>>>(po, w_out, out, ROWS_, DIM_, DIM_);
}